// round 10
// baseline (speedup 1.0000x reference)
#include <cuda_runtime.h>
#include <cuda_fp16.h>

#define N_NODES 50000
#define N_EDGES 1000000
#define D_IN    64
#define D_HID   64
#define D_OUTF  32

// ---- scratch (no allocs). Device globals referenced ONLY in device code. ----
__device__ float  g_deg [N_NODES];
__device__ __half g_h16 [N_NODES * D_HID];  // hs = dinv*(X@W), fp16 (stride 64 L1, 32 L2)
__device__ float  g_agg [N_NODES * D_HID];  // layer-1 aggregation (fp32)

__device__ __forceinline__ void red_add_v4(float* p, float4 v) {
    asm volatile("red.global.add.v4.f32 [%0], {%1, %2, %3, %4};"
                 :: "l"(p), "f"(v.x), "f"(v.y), "f"(v.z), "f"(v.w) : "memory");
}

__device__ __forceinline__ unsigned int h2u(__half2 h) {
    return *reinterpret_cast<unsigned int*>(&h);
}

// ---------------- degree ----------------
__global__ void k_deg_init() {
    int i = blockIdx.x * blockDim.x + threadIdx.x;
    if (i < N_NODES) g_deg[i] = 1.0f;          // self-loop weight
}

__global__ void k_deg_count(const int* __restrict__ dst, const float* __restrict__ w) {
    int t = blockIdx.x * blockDim.x + threadIdx.x;
    int e0 = t * 4;
#pragma unroll
    for (int j = 0; j < 4; j++) {
        int e = e0 + j;
        if (e < N_EDGES) atomicAdd(&g_deg[dst[e]], w[e]);
    }
}

// ---------------- GEMM L1 (64->64): 4x8 per thread ----------------
// Writes h fp16 to g_h16 and fp32 self-loop init to g_agg.
__global__ __launch_bounds__(128) void k_gemm64(
        const float* __restrict__ X, const float* __restrict__ W) {
    constexpr int DI = 64, DO = 64;
    constexpr int TX = 8, ROWS = 64, XS = ROWS + 4;

    __shared__ float Ws [DI * DO];
    __shared__ float xsT[DI * XS];

    const int tid = threadIdx.x;
    const int tx  = tid % TX;
    const int ty  = tid / TX;
    const int blockRow = blockIdx.x * ROWS;

    for (int i = tid; i < DI * DO / 4; i += 128)
        reinterpret_cast<float4*>(Ws)[i] = reinterpret_cast<const float4*>(W)[i];

    for (int i = tid; i < ROWS * (DI / 4); i += 128) {
        int row = i / (DI / 4);
        int c4  = i % (DI / 4);
        int gr  = blockRow + row;
        float4 v = make_float4(0.f, 0.f, 0.f, 0.f);
        if (gr < N_NODES)
            v = reinterpret_cast<const float4*>(X + gr * DI)[c4];
        xsT[(c4 * 4 + 0) * XS + row] = v.x;
        xsT[(c4 * 4 + 1) * XS + row] = v.y;
        xsT[(c4 * 4 + 2) * XS + row] = v.z;
        xsT[(c4 * 4 + 3) * XS + row] = v.w;
    }
    __syncthreads();

    float acc[4][8];
#pragma unroll
    for (int i = 0; i < 4; i++)
#pragma unroll
        for (int j = 0; j < 8; j++) acc[i][j] = 0.0f;

#pragma unroll
    for (int k = 0; k < DI; k++) {
        float4 a  = *reinterpret_cast<const float4*>(&xsT[k * XS + ty * 4]);
        float4 b0 = *reinterpret_cast<const float4*>(&Ws [k * DO + tx * 8]);
        float4 b1 = *reinterpret_cast<const float4*>(&Ws [k * DO + tx * 8 + 4]);
        float av[4] = {a.x, a.y, a.z, a.w};
        float bv[8] = {b0.x, b0.y, b0.z, b0.w, b1.x, b1.y, b1.z, b1.w};
#pragma unroll
        for (int i = 0; i < 4; i++)
#pragma unroll
            for (int j = 0; j < 8; j++)
                acc[i][j] += av[i] * bv[j];
    }

#pragma unroll
    for (int i = 0; i < 4; i++) {
        int row = blockRow + ty * 4 + i;
        if (row >= N_NODES) break;
        float dv = rsqrtf(g_deg[row]);
        float v[8];
#pragma unroll
        for (int j = 0; j < 8; j++) v[j] = dv * acc[i][j];
        // fp32 self-loop init
        *reinterpret_cast<float4*>(&g_agg[row * DO + tx * 8])
            = make_float4(v[0], v[1], v[2], v[3]);
        *reinterpret_cast<float4*>(&g_agg[row * DO + tx * 8 + 4])
            = make_float4(v[4], v[5], v[6], v[7]);
        // fp16 h (8 halves = 16B)
        uint4 hp;
        hp.x = h2u(__float22half2_rn(make_float2(v[0], v[1])));
        hp.y = h2u(__float22half2_rn(make_float2(v[2], v[3])));
        hp.z = h2u(__float22half2_rn(make_float2(v[4], v[5])));
        hp.w = h2u(__float22half2_rn(make_float2(v[6], v[7])));
        *reinterpret_cast<uint4*>(&g_h16[row * DO + tx * 8]) = hp;
    }
}

// ---------------- GEMM L2 (64->32), input fused with final1 ----------------
// Loads g_agg, applies relu(rsqrt(deg)*v + b1) on the fly, computes @W2,
// writes h fp16 (stride 32) and fp32 self-loop init to OUT.
__global__ __launch_bounds__(256) void k_gemm32(const float* __restrict__ W,
                                                const float* __restrict__ b1,
                                                float* __restrict__ OUT) {
    constexpr int DI = 64, DO = 32;
    constexpr int TX = 8, ROWS = 128, XS = ROWS + 4;

    __shared__ float Ws [DI * DO];
    __shared__ float xsT[DI * XS];

    const int tid = threadIdx.x;
    const int tx  = tid % TX;
    const int ty  = tid / TX;
    const int blockRow = blockIdx.x * ROWS;

    for (int i = tid; i < DI * DO / 4; i += 256)
        reinterpret_cast<float4*>(Ws)[i] = reinterpret_cast<const float4*>(W)[i];

    for (int i = tid; i < ROWS * (DI / 4); i += 256) {
        int row = i / (DI / 4);
        int c4  = i % (DI / 4);
        int gr  = blockRow + row;
        float4 v = make_float4(0.f, 0.f, 0.f, 0.f);
        if (gr < N_NODES) {
            v = reinterpret_cast<const float4*>(g_agg + gr * DI)[c4];
            float  dv = rsqrtf(g_deg[gr]);
            float4 bb = __ldg(&reinterpret_cast<const float4*>(b1)[c4]);
            v.x = fmaxf(dv * v.x + bb.x, 0.0f);
            v.y = fmaxf(dv * v.y + bb.y, 0.0f);
            v.z = fmaxf(dv * v.z + bb.z, 0.0f);
            v.w = fmaxf(dv * v.w + bb.w, 0.0f);
        }
        xsT[(c4 * 4 + 0) * XS + row] = v.x;
        xsT[(c4 * 4 + 1) * XS + row] = v.y;
        xsT[(c4 * 4 + 2) * XS + row] = v.z;
        xsT[(c4 * 4 + 3) * XS + row] = v.w;
    }
    __syncthreads();

    float acc[4][4];
#pragma unroll
    for (int i = 0; i < 4; i++)
#pragma unroll
        for (int j = 0; j < 4; j++) acc[i][j] = 0.0f;

#pragma unroll
    for (int k = 0; k < DI; k++) {
        float4 a = *reinterpret_cast<const float4*>(&xsT[k * XS + ty * 4]);
        float4 b = *reinterpret_cast<const float4*>(&Ws [k * DO + tx * 4]);
        acc[0][0] += a.x * b.x; acc[0][1] += a.x * b.y; acc[0][2] += a.x * b.z; acc[0][3] += a.x * b.w;
        acc[1][0] += a.y * b.x; acc[1][1] += a.y * b.y; acc[1][2] += a.y * b.z; acc[1][3] += a.y * b.w;
        acc[2][0] += a.z * b.x; acc[2][1] += a.z * b.y; acc[2][2] += a.z * b.z; acc[2][3] += a.z * b.w;
        acc[3][0] += a.w * b.x; acc[3][1] += a.w * b.y; acc[3][2] += a.w * b.z; acc[3][3] += a.w * b.w;
    }

#pragma unroll
    for (int i = 0; i < 4; i++) {
        int row = blockRow + ty * 4 + i;
        if (row >= N_NODES) break;
        float dv = rsqrtf(g_deg[row]);
        float4 v = make_float4(dv * acc[i][0], dv * acc[i][1],
                               dv * acc[i][2], dv * acc[i][3]);
        *reinterpret_cast<float4*>(&OUT[row * DO + tx * 4]) = v;   // self-loop init
        uint2 hp;
        hp.x = h2u(__float22half2_rn(make_float2(v.x, v.y)));
        hp.y = h2u(__float22half2_rn(make_float2(v.z, v.w)));
        *reinterpret_cast<uint2*>(&g_h16[row * DO + tx * 4]) = hp;
    }
}

// ---------------- edge scatter, fp16 reads: AGG[dst] += w * h16[src] ----------------
// D=64: TPE=8, thread p covers 8 cols (16B fp16 read, 2x red.v4 fp32).
template <int LAYER>
__global__ void k_scatter64(const int* __restrict__ src,
                            const int* __restrict__ dst,
                            const float* __restrict__ w,
                            float* __restrict__ aggParam) {
    constexpr int TPE = 8, HALF = N_EDGES / 2;
    int tid = blockIdx.x * blockDim.x + threadIdx.x;
    int e = tid / TPE;
    int p = tid % TPE;
    if (e >= HALF) return;
    float* AGG = (LAYER == 1) ? g_agg : aggParam;

#pragma unroll
    for (int half = 0; half < 2; half++) {
        int ee = e + half * HALF;
        int   s  = __ldg(&src[ee]);
        int   d  = __ldg(&dst[ee]);
        float we = __ldg(&w[ee]);
        uint4 hp = *reinterpret_cast<const uint4*>(&g_h16[s * 64 + p * 8]);
        float2 f0 = __half22float2(*reinterpret_cast<__half2*>(&hp.x));
        float2 f1 = __half22float2(*reinterpret_cast<__half2*>(&hp.y));
        float2 f2 = __half22float2(*reinterpret_cast<__half2*>(&hp.z));
        float2 f3 = __half22float2(*reinterpret_cast<__half2*>(&hp.w));
        red_add_v4(AGG + d * 64 + p * 8,
                   make_float4(we*f0.x, we*f0.y, we*f1.x, we*f1.y));
        red_add_v4(AGG + d * 64 + p * 8 + 4,
                   make_float4(we*f2.x, we*f2.y, we*f3.x, we*f3.y));
    }
}

// D=32: TPE=4, thread p covers 8 cols.
__global__ void k_scatter32(const int* __restrict__ src,
                            const int* __restrict__ dst,
                            const float* __restrict__ w,
                            float* __restrict__ OUT) {
    constexpr int TPE = 4, HALF = N_EDGES / 2;
    int tid = blockIdx.x * blockDim.x + threadIdx.x;
    int e = tid / TPE;
    int p = tid % TPE;
    if (e >= HALF) return;

#pragma unroll
    for (int half = 0; half < 2; half++) {
        int ee = e + half * HALF;
        int   s  = __ldg(&src[ee]);
        int   d  = __ldg(&dst[ee]);
        float we = __ldg(&w[ee]);
        uint4 hp = *reinterpret_cast<const uint4*>(&g_h16[s * 32 + p * 8]);
        float2 f0 = __half22float2(*reinterpret_cast<__half2*>(&hp.x));
        float2 f1 = __half22float2(*reinterpret_cast<__half2*>(&hp.y));
        float2 f2 = __half22float2(*reinterpret_cast<__half2*>(&hp.z));
        float2 f3 = __half22float2(*reinterpret_cast<__half2*>(&hp.w));
        red_add_v4(OUT + d * 32 + p * 8,
                   make_float4(we*f0.x, we*f0.y, we*f1.x, we*f1.y));
        red_add_v4(OUT + d * 32 + p * 8 + 4,
                   make_float4(we*f2.x, we*f2.y, we*f3.x, we*f3.y));
    }
}

// ---------------- finalize layer 2: OUT = relu(rsqrt(deg)*OUT + b2) ----------------
__global__ void k_final2(float* __restrict__ OUT, const float* __restrict__ b) {
    int i = blockIdx.x * blockDim.x + threadIdx.x;
    if (i >= N_NODES * D_OUTF) return;
    int row = i / D_OUTF, col = i % D_OUTF;
    float v = rsqrtf(g_deg[row]) * OUT[i] + b[col];
    OUT[i] = fmaxf(v, 0.0f);
}

extern "C" void kernel_launch(void* const* d_in, const int* in_sizes, int n_in,
                              void* d_out, int out_size) {
    const float* x   = (const float*)d_in[0];
    const int*   ei  = (const int*)  d_in[1];   // [2, E]
    const float* ew  = (const float*)d_in[2];
    const float* W1  = (const float*)d_in[3];
    const float* b1  = (const float*)d_in[4];
    const float* W2  = (const float*)d_in[5];
    const float* b2  = (const float*)d_in[6];
    float*       out = (float*)d_out;

    const int* src = ei;
    const int* dst = ei + N_EDGES;

    k_deg_init <<<(N_NODES + 255) / 256, 256>>>();
    k_deg_count<<<(N_EDGES / 4 + 255) / 256, 256>>>(dst, ew);

    // ---- layer 1 ----
    k_gemm64<<<(N_NODES + 63) / 64, 128>>>(x, W1);
    {
        int nthr = (N_EDGES / 2) * 8;
        k_scatter64<1><<<(nthr + 255) / 256, 256>>>(src, dst, ew, nullptr);
    }

    // ---- layer 2 (final1 fused into gemm32 input) ----
    k_gemm32<<<(N_NODES + 127) / 128, 256>>>(W2, b1, out);
    {
        int nthr = (N_EDGES / 2) * 4;
        k_scatter32<<<(nthr + 255) / 256, 256>>>(src, dst, ew, out);
    }
    k_final2<<<(N_NODES * D_OUTF + 255) / 256, 256>>>(out, b2);
}

// round 11
// speedup vs baseline: 1.2496x; 1.2496x over previous
#include <cuda_runtime.h>
#include <cuda_fp16.h>

#define N_NODES 50000
#define N_EDGES 1000000
#define D_IN    64
#define D_HID   64
#define D_OUTF  32

// ---- scratch (no allocs). Device globals referenced ONLY in device code. ----
__device__ float  g_deg [N_NODES];
__device__ __half g_h16 [N_NODES * D_HID];  // hs = dinv*(X@W), fp16
__device__ float  g_agg [N_NODES * D_HID];  // layer-1 aggregation (fp32)

__device__ __forceinline__ void red_add_v4(float* p, float4 v) {
    asm volatile("red.global.add.v4.f32 [%0], {%1, %2, %3, %4};"
                 :: "l"(p), "f"(v.x), "f"(v.y), "f"(v.z), "f"(v.w) : "memory");
}

__device__ __forceinline__ unsigned int h2u(__half2 h) {
    return *reinterpret_cast<unsigned int*>(&h);
}

// ---------------- degree ----------------
__global__ void k_deg_init() {
    int i = blockIdx.x * blockDim.x + threadIdx.x;
    if (i < N_NODES) g_deg[i] = 1.0f;          // self-loop weight
}

__global__ void k_deg_count(const int* __restrict__ dst, const float* __restrict__ w) {
    int t = blockIdx.x * blockDim.x + threadIdx.x;
    int e0 = t * 4;
#pragma unroll
    for (int j = 0; j < 4; j++) {
        int e = e0 + j;
        if (e < N_EDGES) atomicAdd(&g_deg[dst[e]], w[e]);
    }
}

// ---------------- GEMM L1 (64->64): 4x8 per thread ----------------
__global__ __launch_bounds__(128) void k_gemm64(
        const float* __restrict__ X, const float* __restrict__ W) {
    constexpr int DI = 64, DO = 64;
    constexpr int TX = 8, ROWS = 64, XS = ROWS + 4;

    __shared__ float Ws [DI * DO];
    __shared__ float xsT[DI * XS];

    const int tid = threadIdx.x;
    const int tx  = tid % TX;
    const int ty  = tid / TX;
    const int blockRow = blockIdx.x * ROWS;

    for (int i = tid; i < DI * DO / 4; i += 128)
        reinterpret_cast<float4*>(Ws)[i] = reinterpret_cast<const float4*>(W)[i];

    for (int i = tid; i < ROWS * (DI / 4); i += 128) {
        int row = i / (DI / 4);
        int c4  = i % (DI / 4);
        int gr  = blockRow + row;
        float4 v = make_float4(0.f, 0.f, 0.f, 0.f);
        if (gr < N_NODES)
            v = reinterpret_cast<const float4*>(X + gr * DI)[c4];
        xsT[(c4 * 4 + 0) * XS + row] = v.x;
        xsT[(c4 * 4 + 1) * XS + row] = v.y;
        xsT[(c4 * 4 + 2) * XS + row] = v.z;
        xsT[(c4 * 4 + 3) * XS + row] = v.w;
    }
    __syncthreads();

    float acc[4][8];
#pragma unroll
    for (int i = 0; i < 4; i++)
#pragma unroll
        for (int j = 0; j < 8; j++) acc[i][j] = 0.0f;

#pragma unroll
    for (int k = 0; k < DI; k++) {
        float4 a  = *reinterpret_cast<const float4*>(&xsT[k * XS + ty * 4]);
        float4 b0 = *reinterpret_cast<const float4*>(&Ws [k * DO + tx * 8]);
        float4 b1 = *reinterpret_cast<const float4*>(&Ws [k * DO + tx * 8 + 4]);
        float av[4] = {a.x, a.y, a.z, a.w};
        float bv[8] = {b0.x, b0.y, b0.z, b0.w, b1.x, b1.y, b1.z, b1.w};
#pragma unroll
        for (int i = 0; i < 4; i++)
#pragma unroll
            for (int j = 0; j < 8; j++)
                acc[i][j] += av[i] * bv[j];
    }

#pragma unroll
    for (int i = 0; i < 4; i++) {
        int row = blockRow + ty * 4 + i;
        if (row >= N_NODES) break;
        float dv = rsqrtf(g_deg[row]);
        float v[8];
#pragma unroll
        for (int j = 0; j < 8; j++) v[j] = dv * acc[i][j];
        *reinterpret_cast<float4*>(&g_agg[row * DO + tx * 8])
            = make_float4(v[0], v[1], v[2], v[3]);
        *reinterpret_cast<float4*>(&g_agg[row * DO + tx * 8 + 4])
            = make_float4(v[4], v[5], v[6], v[7]);
        uint4 hp;
        hp.x = h2u(__float22half2_rn(make_float2(v[0], v[1])));
        hp.y = h2u(__float22half2_rn(make_float2(v[2], v[3])));
        hp.z = h2u(__float22half2_rn(make_float2(v[4], v[5])));
        hp.w = h2u(__float22half2_rn(make_float2(v[6], v[7])));
        *reinterpret_cast<uint4*>(&g_h16[row * DO + tx * 8]) = hp;
    }
}

// ---------------- GEMM L2 (64->32), input fused with final1 ----------------
__global__ __launch_bounds__(256) void k_gemm32(const float* __restrict__ W,
                                                const float* __restrict__ b1,
                                                float* __restrict__ OUT) {
    constexpr int DI = 64, DO = 32;
    constexpr int TX = 8, ROWS = 128, XS = ROWS + 4;

    __shared__ float Ws [DI * DO];
    __shared__ float xsT[DI * XS];

    const int tid = threadIdx.x;
    const int tx  = tid % TX;
    const int ty  = tid / TX;
    const int blockRow = blockIdx.x * ROWS;

    for (int i = tid; i < DI * DO / 4; i += 256)
        reinterpret_cast<float4*>(Ws)[i] = reinterpret_cast<const float4*>(W)[i];

    for (int i = tid; i < ROWS * (DI / 4); i += 256) {
        int row = i / (DI / 4);
        int c4  = i % (DI / 4);
        int gr  = blockRow + row;
        float4 v = make_float4(0.f, 0.f, 0.f, 0.f);
        if (gr < N_NODES) {
            v = reinterpret_cast<const float4*>(g_agg + gr * DI)[c4];
            float  dv = rsqrtf(g_deg[gr]);
            float4 bb = __ldg(&reinterpret_cast<const float4*>(b1)[c4]);
            v.x = fmaxf(dv * v.x + bb.x, 0.0f);
            v.y = fmaxf(dv * v.y + bb.y, 0.0f);
            v.z = fmaxf(dv * v.z + bb.z, 0.0f);
            v.w = fmaxf(dv * v.w + bb.w, 0.0f);
        }
        xsT[(c4 * 4 + 0) * XS + row] = v.x;
        xsT[(c4 * 4 + 1) * XS + row] = v.y;
        xsT[(c4 * 4 + 2) * XS + row] = v.z;
        xsT[(c4 * 4 + 3) * XS + row] = v.w;
    }
    __syncthreads();

    float acc[4][4];
#pragma unroll
    for (int i = 0; i < 4; i++)
#pragma unroll
        for (int j = 0; j < 4; j++) acc[i][j] = 0.0f;

#pragma unroll
    for (int k = 0; k < DI; k++) {
        float4 a = *reinterpret_cast<const float4*>(&xsT[k * XS + ty * 4]);
        float4 b = *reinterpret_cast<const float4*>(&Ws [k * DO + tx * 4]);
        acc[0][0] += a.x * b.x; acc[0][1] += a.x * b.y; acc[0][2] += a.x * b.z; acc[0][3] += a.x * b.w;
        acc[1][0] += a.y * b.x; acc[1][1] += a.y * b.y; acc[1][2] += a.y * b.z; acc[1][3] += a.y * b.w;
        acc[2][0] += a.z * b.x; acc[2][1] += a.z * b.y; acc[2][2] += a.z * b.z; acc[2][3] += a.z * b.w;
        acc[3][0] += a.w * b.x; acc[3][1] += a.w * b.y; acc[3][2] += a.w * b.z; acc[3][3] += a.w * b.w;
    }

#pragma unroll
    for (int i = 0; i < 4; i++) {
        int row = blockRow + ty * 4 + i;
        if (row >= N_NODES) break;
        float dv = rsqrtf(g_deg[row]);
        float4 v = make_float4(dv * acc[i][0], dv * acc[i][1],
                               dv * acc[i][2], dv * acc[i][3]);
        *reinterpret_cast<float4*>(&OUT[row * DO + tx * 4]) = v;   // self-loop init
        uint2 hp;
        hp.x = h2u(__float22half2_rn(make_float2(v.x, v.y)));
        hp.y = h2u(__float22half2_rn(make_float2(v.z, v.w)));
        *reinterpret_cast<uint2*>(&g_h16[row * DO + tx * 4]) = hp;
    }
}

// ---------------- edge scatter: R8 structure, fp16 reads ----------------
// D=64: TPE=16, thread p covers 4 cols: 1x LDG.64 (4 halves) + 1x RED.v4 per edge,
// 2 independent edges (opposite halves of the edge list) per thread.
template <int LAYER>
__global__ void k_scatter64(const int* __restrict__ src,
                            const int* __restrict__ dst,
                            const float* __restrict__ w,
                            float* __restrict__ aggParam) {
    constexpr int TPE = 16, HALF = N_EDGES / 2;
    int tid = blockIdx.x * blockDim.x + threadIdx.x;
    int e = tid / TPE;
    int p = tid % TPE;
    if (e >= HALF) return;
    float* AGG = (LAYER == 1) ? g_agg : aggParam;

    int eB = e + HALF;
    int   sA = __ldg(&src[e]),  dA = __ldg(&dst[e]);  float wA = __ldg(&w[e]);
    int   sB = __ldg(&src[eB]), dB = __ldg(&dst[eB]); float wB = __ldg(&w[eB]);

    uint2 ha = *reinterpret_cast<const uint2*>(&g_h16[sA * 64 + p * 4]);
    uint2 hb = *reinterpret_cast<const uint2*>(&g_h16[sB * 64 + p * 4]);
    float2 a0 = __half22float2(*reinterpret_cast<__half2*>(&ha.x));
    float2 a1 = __half22float2(*reinterpret_cast<__half2*>(&ha.y));
    float2 b0 = __half22float2(*reinterpret_cast<__half2*>(&hb.x));
    float2 b1 = __half22float2(*reinterpret_cast<__half2*>(&hb.y));
    red_add_v4(AGG + dA * 64 + p * 4, make_float4(wA*a0.x, wA*a0.y, wA*a1.x, wA*a1.y));
    red_add_v4(AGG + dB * 64 + p * 4, make_float4(wB*b0.x, wB*b0.y, wB*b1.x, wB*b1.y));
}

// D=32: TPE=8, thread p covers 4 cols.
__global__ void k_scatter32(const int* __restrict__ src,
                            const int* __restrict__ dst,
                            const float* __restrict__ w,
                            float* __restrict__ OUT) {
    constexpr int TPE = 8, HALF = N_EDGES / 2;
    int tid = blockIdx.x * blockDim.x + threadIdx.x;
    int e = tid / TPE;
    int p = tid % TPE;
    if (e >= HALF) return;

    int eB = e + HALF;
    int   sA = __ldg(&src[e]),  dA = __ldg(&dst[e]);  float wA = __ldg(&w[e]);
    int   sB = __ldg(&src[eB]), dB = __ldg(&dst[eB]); float wB = __ldg(&w[eB]);

    uint2 ha = *reinterpret_cast<const uint2*>(&g_h16[sA * 32 + p * 4]);
    uint2 hb = *reinterpret_cast<const uint2*>(&g_h16[sB * 32 + p * 4]);
    float2 a0 = __half22float2(*reinterpret_cast<__half2*>(&ha.x));
    float2 a1 = __half22float2(*reinterpret_cast<__half2*>(&ha.y));
    float2 b0 = __half22float2(*reinterpret_cast<__half2*>(&hb.x));
    float2 b1 = __half22float2(*reinterpret_cast<__half2*>(&hb.y));
    red_add_v4(OUT + dA * 32 + p * 4, make_float4(wA*a0.x, wA*a0.y, wA*a1.x, wA*a1.y));
    red_add_v4(OUT + dB * 32 + p * 4, make_float4(wB*b0.x, wB*b0.y, wB*b1.x, wB*b1.y));
}

// ---------------- finalize layer 2 ----------------
__global__ void k_final2(float* __restrict__ OUT, const float* __restrict__ b) {
    int i = blockIdx.x * blockDim.x + threadIdx.x;
    if (i >= N_NODES * D_OUTF) return;
    int row = i / D_OUTF, col = i % D_OUTF;
    float v = rsqrtf(g_deg[row]) * OUT[i] + b[col];
    OUT[i] = fmaxf(v, 0.0f);
}

extern "C" void kernel_launch(void* const* d_in, const int* in_sizes, int n_in,
                              void* d_out, int out_size) {
    const float* x   = (const float*)d_in[0];
    const int*   ei  = (const int*)  d_in[1];   // [2, E]
    const float* ew  = (const float*)d_in[2];
    const float* W1  = (const float*)d_in[3];
    const float* b1  = (const float*)d_in[4];
    const float* W2  = (const float*)d_in[5];
    const float* b2  = (const float*)d_in[6];
    float*       out = (float*)d_out;

    const int* src = ei;
    const int* dst = ei + N_EDGES;

    k_deg_init <<<(N_NODES + 255) / 256, 256>>>();
    k_deg_count<<<(N_EDGES / 4 + 255) / 256, 256>>>(dst, ew);

    // ---- layer 1 ----
    k_gemm64<<<(N_NODES + 63) / 64, 128>>>(x, W1);
    {
        int nthr = (N_EDGES / 2) * 16;
        k_scatter64<1><<<(nthr + 255) / 256, 256>>>(src, dst, ew, nullptr);
    }

    // ---- layer 2 (final1 fused into gemm32 input) ----
    k_gemm32<<<(N_NODES + 127) / 128, 256>>>(W2, b1, out);
    {
        int nthr = (N_EDGES / 2) * 8;
        k_scatter32<<<(nthr + 255) / 256, 256>>>(src, dst, ew, out);
    }
    k_final2<<<(N_NODES * D_OUTF + 255) / 256, 256>>>(out, b2);
}